// round 1
// baseline (speedup 1.0000x reference)
#include <cuda_runtime.h>
#include <math.h>

typedef unsigned long long ull;

#define BB   8
#define FHH  8
#define NN   2048
#define TINN 5
#define HH1  32
#define HH2  64
#define KXX  40      // TIN*FH
#define NEGV -9e15f

// ---------------- scratch (device globals; no allocation allowed) ----------
__device__ float g_h1[BB*NN*HH1];   // [t][n][j]
__device__ float g_hs[BB*NN*HH2];   // [t][n][u]
__device__ float g_Wh[BB*NN*HH2];   // [t][n][c]
__device__ float g_s [BB*NN];
__device__ float g_d [BB*NN];

// ---------------- packed f32x2 helpers (Blackwell) --------------------------
__device__ __forceinline__ ull pack2(float lo, float hi) {
    ull r; asm("mov.b64 %0, {%1, %2};" : "=l"(r) : "f"(lo), "f"(hi)); return r;
}
__device__ __forceinline__ void unpack2(ull v, float& lo, float& hi) {
    asm("mov.b64 {%0, %1}, %2;" : "=f"(lo), "=f"(hi) : "l"(v));
}
__device__ __forceinline__ ull ffma2(ull a, ull b, ull c) {
    ull r; asm("fma.rn.f32x2 %0, %1, %2, %3;" : "=l"(r) : "l"(a), "l"(b), "l"(c)); return r;
}
__device__ __forceinline__ ull fmul2(ull a, ull b) {
    ull r; asm("mul.rn.f32x2 %0, %1, %2;" : "=l"(r) : "l"(a), "l"(b)); return r;
}

// ============================================================================
// Kernel 1: h1[t,n,k] = elu( sum_idx x[t,n,idx] * W1[k,idx] + b1[k] )
//           x[t,n, tt*8+f] = hist[t, f, n, tt]
// 2048 blocks x 256 threads; 8 rows/block, 32 output-units per row.
// ============================================================================
__global__ void k_h1(const float* __restrict__ hist,
                     const float* __restrict__ W1,
                     const float* __restrict__ b1) {
    __shared__ float w1s[KXX*HH1];   // transposed: [idx][k] -> conflict-free
    for (int i = threadIdx.x; i < HH1*KXX; i += 256) {
        int k = i / KXX, idx = i % KXX;
        w1s[idx*HH1 + k] = W1[i];
    }
    __syncthreads();
    int row = blockIdx.x * 8 + (threadIdx.x >> 5);   // over B*N = 16384
    int k   = threadIdx.x & 31;
    int t = row / NN, n = row % NN;
    float acc = b1[k];
    #pragma unroll
    for (int tt = 0; tt < TINN; tt++) {
        #pragma unroll
        for (int f = 0; f < FHH; f++) {
            float x = hist[((t*FHH + f)*NN + n)*TINN + tt];
            acc = fmaf(x, w1s[(tt*FHH + f)*HH1 + k], acc);
        }
    }
    acc = acc > 0.f ? acc : expm1f(acc);
    g_h1[row*HH1 + k] = acc;
}

// ============================================================================
// Kernel 2: LSTM, 8 steps, gate order i,f,g,o.
// 128 blocks x 256 threads; block = 16 nodes. Weights transposed in dyn smem.
// thread -> (m = tid&15 node, u0 = (tid>>4)*4 output-unit quad), 16 gate accs
// held as 8 f32x2 pairs. c state lives in registers across steps.
// ============================================================================
__global__ void k_lstm(const float* __restrict__ W_ih, const float* __restrict__ W_hh,
                       const float* __restrict__ b_ih, const float* __restrict__ b_hh) {
    extern __shared__ float sm[];
    float* wih  = sm;                 // [32][256]
    float* whh  = wih + 32*256;       // [64][256]
    float* bsum = whh + 64*256;       // [256]
    float* h1s  = bsum + 256;         // [32][17]
    float* hsh  = h1s + 32*17;        // [64][17]

    int tid = threadIdx.x;
    for (int i = tid; i < 256*32; i += 256) { int k = i >> 5, j = i & 31; wih[j*256 + k] = W_ih[i]; }
    for (int i = tid; i < 256*64; i += 256) { int k = i >> 6, j = i & 63; whh[j*256 + k] = W_hh[i]; }
    bsum[tid] = b_ih[tid] + b_hh[tid];
    for (int i = tid; i < 64*17; i += 256) hsh[i] = 0.f;

    int m  = tid & 15;
    int u0 = (tid >> 4) * 4;
    int node = blockIdx.x * 16 + m;

    float c[4] = {0.f, 0.f, 0.f, 0.f};

    for (int t = 0; t < BB; t++) {
        __syncthreads();
        for (int i = tid; i < 512; i += 256) {
            int mm = i >> 5, j = i & 31;
            h1s[j*17 + mm] = g_h1[(t*NN + blockIdx.x*16 + mm)*HH1 + j];
        }
        __syncthreads();

        ull acc[4][2];
        #pragma unroll
        for (int gt = 0; gt < 4; gt++) {
            acc[gt][0] = *(const ull*)&bsum[gt*64 + u0];
            acc[gt][1] = *(const ull*)&bsum[gt*64 + u0 + 2];
        }
        #pragma unroll 4
        for (int j = 0; j < 32; j++) {
            float hv = h1s[j*17 + m];
            ull hv2 = pack2(hv, hv);
            const float* wr = &wih[j*256];
            #pragma unroll
            for (int gt = 0; gt < 4; gt++) {
                acc[gt][0] = ffma2(*(const ull*)&wr[gt*64 + u0],     hv2, acc[gt][0]);
                acc[gt][1] = ffma2(*(const ull*)&wr[gt*64 + u0 + 2], hv2, acc[gt][1]);
            }
        }
        #pragma unroll 4
        for (int j = 0; j < 64; j++) {
            float hv = hsh[j*17 + m];
            ull hv2 = pack2(hv, hv);
            const float* wr = &whh[j*256];
            #pragma unroll
            for (int gt = 0; gt < 4; gt++) {
                acc[gt][0] = ffma2(*(const ull*)&wr[gt*64 + u0],     hv2, acc[gt][0]);
                acc[gt][1] = ffma2(*(const ull*)&wr[gt*64 + u0 + 2], hv2, acc[gt][1]);
            }
        }
        float gv[4][4];
        #pragma unroll
        for (int gt = 0; gt < 4; gt++) {
            unpack2(acc[gt][0], gv[gt][0], gv[gt][1]);
            unpack2(acc[gt][1], gv[gt][2], gv[gt][3]);
        }
        __syncthreads();   // everyone done reading old hsh
        float hout[4];
        #pragma unroll
        for (int q = 0; q < 4; q++) {
            float ig = 1.f / (1.f + __expf(-gv[0][q]));
            float fg = 1.f / (1.f + __expf(-gv[1][q]));
            float gg = tanhf(gv[2][q]);
            float og = 1.f / (1.f + __expf(-gv[3][q]));
            c[q] = fg * c[q] + ig * gg;
            float h = og * tanhf(c[q]);
            hsh[(u0 + q)*17 + m] = h;
            hout[q] = h;
        }
        *(float4*)&g_hs[(t*NN + node)*HH2 + u0] =
            make_float4(hout[0], hout[1], hout[2], hout[3]);
    }
}

// ============================================================================
// Kernel 3: Wh = hs @ Wg ; s = Wh.a_src ; d = Wh.a_dst
// 1024 blocks x 256 threads; block = 16 rows of (t,n).
// ============================================================================
__global__ void k_wh(const float* __restrict__ Wg,
                     const float* __restrict__ a_src,
                     const float* __restrict__ a_dst) {
    __shared__ float wgs[64*64];
    __shared__ float hss[64*17];
    __shared__ float ps[16*17];
    __shared__ float pd[16*17];
    int tid = threadIdx.x;
    int row0 = blockIdx.x * 16;
    for (int i = tid; i < 4096; i += 256) wgs[i] = Wg[i];
    for (int i = tid; i < 1024; i += 256) {
        int mm = i >> 6, u = i & 63;
        hss[u*17 + mm] = g_hs[(row0 + mm)*HH2 + u];
    }
    __syncthreads();
    int m  = tid >> 4;       // row within tile (coalesced stores over cq)
    int cq = tid & 15;
    int c0 = cq * 4;
    ull acc0 = 0ull, acc1 = 0ull;
    #pragma unroll 8
    for (int u = 0; u < 64; u++) {
        float hv = hss[u*17 + m];
        ull hv2 = pack2(hv, hv);
        acc0 = ffma2(*(const ull*)&wgs[u*64 + c0],     hv2, acc0);
        acc1 = ffma2(*(const ull*)&wgs[u*64 + c0 + 2], hv2, acc1);
    }
    float wh[4];
    unpack2(acc0, wh[0], wh[1]);
    unpack2(acc1, wh[2], wh[3]);
    *(float4*)&g_Wh[(row0 + m)*HH2 + c0] = make_float4(wh[0], wh[1], wh[2], wh[3]);
    float psum = 0.f, dsum = 0.f;
    #pragma unroll
    for (int q = 0; q < 4; q++) {
        psum = fmaf(wh[q], a_src[c0 + q], psum);
        dsum = fmaf(wh[q], a_dst[c0 + q], dsum);
    }
    ps[m*17 + cq] = psum;
    pd[m*17 + cq] = dsum;
    __syncthreads();
    if (tid < 16) {
        float s = 0.f, d = 0.f;
        #pragma unroll
        for (int q = 0; q < 16; q++) { s += ps[tid*17 + q]; d += pd[tid*17 + q]; }
        g_s[row0 + tid] = s;
        g_d[row0 + tid] = d;
    }
}

// ============================================================================
// Kernel 4: GAT with online (flash-style) masked softmax + aggregation.
// grid (32, 8): block = (batch b, 64-row tile). 256 threads.
// e_ij = leaky_relu(s_i + d_j, 0.2), masked -> -9e15 (exactly like reference;
// the online rescale handles the all-masked-tile / all-masked-row cases
// exactly). acc tiles 4 rows x 4 cols per thread, f32x2-packed.
// ============================================================================
__global__ void k_gat(const int* __restrict__ adj, float* __restrict__ out) {
    __shared__ float whs[64*64];     // [jj][c]
    __shared__ float Ps [64*64];     // [ii][jj]
    __shared__ float s_sh[64], d_sh[64], m_sh[64], l_sh[64], sc_sh[64];
    int b  = blockIdx.y;
    int i0 = blockIdx.x * 64;
    int tid  = threadIdx.x;
    int lane = tid & 31, w = tid >> 5;

    if (tid < 64) {
        s_sh[tid] = g_s[b*NN + i0 + tid];
        m_sh[tid] = -INFINITY;
        l_sh[tid] = 0.f;
    }

    int ig = tid >> 4;     // 0..15 -> rows ig*4..ig*4+3
    int cg = tid & 15;
    int c0 = cg * 4;
    ull acc[4][2];
    #pragma unroll
    for (int q = 0; q < 4; q++) { acc[q][0] = 0ull; acc[q][1] = 0ull; }

    const int* adjb = adj + (size_t)(b*2 + 1) * NN * NN;

    for (int jt = 0; jt < NN/64; jt++) {
        int j0 = jt * 64;
        __syncthreads();                       // prev-iter readers done
        for (int i = tid; i < 4096; i += 256)
            whs[i] = g_Wh[(b*NN + j0)*HH2 + i];
        if (tid < 64) d_sh[tid] = g_d[b*NN + j0 + tid];
        __syncthreads();

        // ---- phase P: warp w owns rows ii = w*8 .. w*8+7 -------------------
        #pragma unroll
        for (int r = 0; r < 8; r++) {
            int ii = w*8 + r;
            int i  = i0 + ii;
            float si = s_sh[ii];
            const int* arow = adjb + (size_t)i * NN + j0;
            int a1 = arow[lane];
            int a2 = arow[lane + 32];
            float v1 = si + d_sh[lane];
            float v2 = si + d_sh[lane + 32];
            float e1 = v1 > 0.f ? v1 : 0.2f * v1;
            float e2 = v2 > 0.f ? v2 : 0.2f * v2;
            e1 = a1 > 0 ? e1 : NEGV;
            e2 = a2 > 0 ? e2 : NEGV;
            float tm = fmaxf(e1, e2);
            #pragma unroll
            for (int o = 16; o > 0; o >>= 1)
                tm = fmaxf(tm, __shfl_xor_sync(0xffffffffu, tm, o));
            float mold = m_sh[ii];
            float mnew = fmaxf(mold, tm);
            float p1 = __expf(e1 - mnew);
            float p2 = __expf(e2 - mnew);
            float psum = p1 + p2;
            #pragma unroll
            for (int o = 16; o > 0; o >>= 1)
                psum += __shfl_xor_sync(0xffffffffu, psum, o);
            if (lane == 0) {
                float scale = __expf(mold - mnew);
                m_sh[ii]  = mnew;
                l_sh[ii]  = l_sh[ii] * scale + psum;
                sc_sh[ii] = scale;
            }
            Ps[ii*64 + lane]      = p1;
            Ps[ii*64 + lane + 32] = p2;
        }
        __syncthreads();

        // ---- accumulate: acc[q] = acc[q]*scale + sum_jj P[ii][jj]*Wh[jj][c]
        #pragma unroll
        for (int q = 0; q < 4; q++) {
            float sc = sc_sh[ig*4 + q];
            ull sc2 = pack2(sc, sc);
            acc[q][0] = fmul2(acc[q][0], sc2);
            acc[q][1] = fmul2(acc[q][1], sc2);
        }
        #pragma unroll 4
        for (int jj = 0; jj < 64; jj++) {
            ull wa = *(const ull*)&whs[jj*64 + c0];
            ull wb = *(const ull*)&whs[jj*64 + c0 + 2];
            #pragma unroll
            for (int q = 0; q < 4; q++) {
                float p = Ps[(ig*4 + q)*64 + jj];
                ull p2 = pack2(p, p);
                acc[q][0] = ffma2(wa, p2, acc[q][0]);
                acc[q][1] = ffma2(wb, p2, acc[q][1]);
            }
        }
    }
    __syncthreads();

    #pragma unroll
    for (int q = 0; q < 4; q++) {
        int ii = ig*4 + q;
        float linv = 1.f / l_sh[ii];
        float v[4];
        unpack2(acc[q][0], v[0], v[1]);
        unpack2(acc[q][1], v[2], v[3]);
        #pragma unroll
        for (int x = 0; x < 4; x++) {
            float z = v[x] * linv;
            v[x] = z > 0.f ? z : expm1f(z);
        }
        *(float4*)&out[((size_t)b*NN + i0 + ii)*HH2 + c0] =
            make_float4(v[0], v[1], v[2], v[3]);
    }
}

// ============================================================================
extern "C" void kernel_launch(void* const* d_in, const int* in_sizes, int n_in,
                              void* d_out, int out_size) {
    const float* hist  = (const float*)d_in[0];
    const int*   adj   = (const int*)  d_in[1];
    const float* W1    = (const float*)d_in[2];
    const float* b1    = (const float*)d_in[3];
    const float* W_ih  = (const float*)d_in[4];
    const float* W_hh  = (const float*)d_in[5];
    const float* b_ih  = (const float*)d_in[6];
    const float* b_hh  = (const float*)d_in[7];
    const float* Wg    = (const float*)d_in[8];
    const float* a_src = (const float*)d_in[9];
    const float* a_dst = (const float*)d_in[10];
    float* out = (float*)d_out;

    const size_t smem2 = (size_t)(32*256 + 64*256 + 256 + 32*17 + 64*17) * sizeof(float);
    cudaFuncSetAttribute(k_lstm, cudaFuncAttributeMaxDynamicSharedMemorySize, (int)smem2);

    k_h1  <<<2048, 256>>>(hist, W1, b1);
    k_lstm<<<128,  256, smem2>>>(W_ih, W_hh, b_ih, b_hh);
    k_wh  <<<1024, 256>>>(Wg, a_src, a_dst);
    dim3 g4(NN/64, BB);
    k_gat <<<g4, 256>>>(adj, out);
}

// round 2
// speedup vs baseline: 1.1774x; 1.1774x over previous
#include <cuda_runtime.h>
#include <math.h>

typedef unsigned long long ull;

#define BB   8
#define FHH  8
#define NN   2048
#define TINN 5
#define HH1  32
#define HH2  64
#define KXX  40      // TIN*FH
#define NEGV -9e15f
#define SPLIT 4
#define ROWS_TOT (BB*NN)

// ---------------- scratch (device globals; no allocation allowed) ----------
__device__ float g_h1[BB*NN*HH1];   // [t][n][j]
__device__ float g_hs[BB*NN*HH2];   // [t][n][u]
__device__ float g_Wh[BB*NN*HH2];   // [t][n][c]
__device__ float g_s [BB*NN];
__device__ float g_d [BB*NN];
__device__ float g_pm  [SPLIT*ROWS_TOT];          // partial max
__device__ float g_pl  [SPLIT*ROWS_TOT];          // partial l
__device__ float g_pacc[SPLIT*ROWS_TOT*HH2];      // partial unnormalized acc (16.8MB)

// ---------------- packed f32x2 helpers (Blackwell) --------------------------
__device__ __forceinline__ ull pack2(float lo, float hi) {
    ull r; asm("mov.b64 %0, {%1, %2};" : "=l"(r) : "f"(lo), "f"(hi)); return r;
}
__device__ __forceinline__ void unpack2(ull v, float& lo, float& hi) {
    asm("mov.b64 {%0, %1}, %2;" : "=f"(lo), "=f"(hi) : "l"(v));
}
__device__ __forceinline__ ull ffma2(ull a, ull b, ull c) {
    ull r; asm("fma.rn.f32x2 %0, %1, %2, %3;" : "=l"(r) : "l"(a), "l"(b), "l"(c)); return r;
}
__device__ __forceinline__ ull fmul2(ull a, ull b) {
    ull r; asm("mul.rn.f32x2 %0, %1, %2;" : "=l"(r) : "l"(a), "l"(b)); return r;
}

// ============================================================================
// Kernel 1: h1[t,n,k] = elu( sum_idx x[t,n,idx] * W1[k,idx] + b1[k] )
// ============================================================================
__global__ void k_h1(const float* __restrict__ hist,
                     const float* __restrict__ W1,
                     const float* __restrict__ b1) {
    __shared__ float w1s[KXX*HH1];   // transposed: [idx][k]
    for (int i = threadIdx.x; i < HH1*KXX; i += 256) {
        int k = i / KXX, idx = i % KXX;
        w1s[idx*HH1 + k] = W1[i];
    }
    __syncthreads();
    int row = blockIdx.x * 8 + (threadIdx.x >> 5);   // over B*N = 16384
    int k   = threadIdx.x & 31;
    int t = row / NN, n = row % NN;
    float acc = b1[k];
    #pragma unroll
    for (int tt = 0; tt < TINN; tt++) {
        #pragma unroll
        for (int f = 0; f < FHH; f++) {
            float x = hist[((t*FHH + f)*NN + n)*TINN + tt];
            acc = fmaf(x, w1s[(tt*FHH + f)*HH1 + k], acc);
        }
    }
    acc = acc > 0.f ? acc : expm1f(acc);
    g_h1[row*HH1 + k] = acc;
}

// ============================================================================
// Kernel 2: LSTM. 256 blocks x 256 threads; block = 8 nodes.
// thread -> (m = tid>>5 node, u0 = (tid&31)*2 unit pair). Gate accs = 4 ull.
// ============================================================================
#define NPB 8
__global__ void k_lstm(const float* __restrict__ W_ih, const float* __restrict__ W_hh,
                       const float* __restrict__ b_ih, const float* __restrict__ b_hh) {
    extern __shared__ float sm[];
    float* wih  = sm;                 // [32][256]
    float* whh  = wih + 32*256;       // [64][256]
    float* bsum = whh + 64*256;       // [256]
    float* h1s  = bsum + 256;         // [32][9]
    float* hsh  = h1s + 32*9;         // [64][9]

    int tid = threadIdx.x;
    for (int i = tid; i < 256*32; i += 256) { int k = i >> 5, j = i & 31; wih[j*256 + k] = W_ih[i]; }
    for (int i = tid; i < 256*64; i += 256) { int k = i >> 6, j = i & 63; whh[j*256 + k] = W_hh[i]; }
    bsum[tid] = b_ih[tid] + b_hh[tid];
    for (int i = tid; i < 64*9; i += 256) hsh[i] = 0.f;

    int m  = tid >> 5;           // node within block (warp-uniform)
    int u0 = (tid & 31) * 2;     // unit pair -> coalesced stores
    int node = blockIdx.x * NPB + m;

    float c[2] = {0.f, 0.f};

    for (int t = 0; t < BB; t++) {
        __syncthreads();
        {
            int mm = tid >> 5, j = tid & 31;
            h1s[j*9 + mm] = g_h1[(t*NN + blockIdx.x*NPB + mm)*HH1 + j];
        }
        __syncthreads();

        ull acc[4];
        #pragma unroll
        for (int gt = 0; gt < 4; gt++) acc[gt] = *(const ull*)&bsum[gt*64 + u0];

        #pragma unroll 8
        for (int j = 0; j < 32; j++) {
            float hv = h1s[j*9 + m];           // warp broadcast
            ull hv2 = pack2(hv, hv);
            const float* wr = &wih[j*256];
            #pragma unroll
            for (int gt = 0; gt < 4; gt++)
                acc[gt] = ffma2(*(const ull*)&wr[gt*64 + u0], hv2, acc[gt]);
        }
        #pragma unroll 8
        for (int j = 0; j < 64; j++) {
            float hv = hsh[j*9 + m];
            ull hv2 = pack2(hv, hv);
            const float* wr = &whh[j*256];
            #pragma unroll
            for (int gt = 0; gt < 4; gt++)
                acc[gt] = ffma2(*(const ull*)&wr[gt*64 + u0], hv2, acc[gt]);
        }
        float gv[4][2];
        #pragma unroll
        for (int gt = 0; gt < 4; gt++) unpack2(acc[gt], gv[gt][0], gv[gt][1]);

        __syncthreads();   // everyone done reading old hsh
        float hout[2];
        #pragma unroll
        for (int q = 0; q < 2; q++) {
            float ig = 1.f / (1.f + __expf(-gv[0][q]));
            float fg = 1.f / (1.f + __expf(-gv[1][q]));
            float gg = tanhf(gv[2][q]);
            float og = 1.f / (1.f + __expf(-gv[3][q]));
            c[q] = fg * c[q] + ig * gg;
            float h = og * tanhf(c[q]);
            hsh[(u0 + q)*9 + m] = h;
            hout[q] = h;
        }
        *(float2*)&g_hs[(t*NN + node)*HH2 + u0] = make_float2(hout[0], hout[1]);
    }
}

// ============================================================================
// Kernel 3: Wh = hs @ Wg ; s = Wh.a_src ; d = Wh.a_dst
// ============================================================================
__global__ void k_wh(const float* __restrict__ Wg,
                     const float* __restrict__ a_src,
                     const float* __restrict__ a_dst) {
    __shared__ float wgs[64*64];
    __shared__ float hss[64*17];
    __shared__ float ps[16*17];
    __shared__ float pd[16*17];
    int tid = threadIdx.x;
    int row0 = blockIdx.x * 16;
    for (int i = tid; i < 4096; i += 256) wgs[i] = Wg[i];
    for (int i = tid; i < 1024; i += 256) {
        int mm = i >> 6, u = i & 63;
        hss[u*17 + mm] = g_hs[(row0 + mm)*HH2 + u];
    }
    __syncthreads();
    int m  = tid >> 4;
    int cq = tid & 15;
    int c0 = cq * 4;
    ull acc0 = 0ull, acc1 = 0ull;
    #pragma unroll 8
    for (int u = 0; u < 64; u++) {
        float hv = hss[u*17 + m];
        ull hv2 = pack2(hv, hv);
        acc0 = ffma2(*(const ull*)&wgs[u*64 + c0],     hv2, acc0);
        acc1 = ffma2(*(const ull*)&wgs[u*64 + c0 + 2], hv2, acc1);
    }
    float wh[4];
    unpack2(acc0, wh[0], wh[1]);
    unpack2(acc1, wh[2], wh[3]);
    *(float4*)&g_Wh[(row0 + m)*HH2 + c0] = make_float4(wh[0], wh[1], wh[2], wh[3]);
    float psum = 0.f, dsum = 0.f;
    #pragma unroll
    for (int q = 0; q < 4; q++) {
        psum = fmaf(wh[q], a_src[c0 + q], psum);
        dsum = fmaf(wh[q], a_dst[c0 + q], dsum);
    }
    ps[m*17 + cq] = psum;
    pd[m*17 + cq] = dsum;
    __syncthreads();
    if (tid < 16) {
        float s = 0.f, d = 0.f;
        #pragma unroll
        for (int q = 0; q < 16; q++) { s += ps[tid*17 + q]; d += pd[tid*17 + q]; }
        g_s[row0 + tid] = s;
        g_d[row0 + tid] = d;
    }
}

// ============================================================================
// Kernel 4: split-K GAT, online masked softmax. grid (32, 8, SPLIT).
// Each block handles 8 of 32 j-tiles, emits partial (m, l, unnormalized acc).
// P stored in smem as duplicated f32x2 pairs to kill pack-mov overhead.
// ============================================================================
__global__ void k_gat(const int* __restrict__ adj) {
    __shared__ float whs[64*64];     // [jj][c]
    __shared__ ull   Ps2[64*64];     // [ii][jj] duplicated pairs (32KB)
    __shared__ float s_sh[64], d_sh[64], m_sh[64], l_sh[64], sc_sh[64];
    int b   = blockIdx.y;
    int i0  = blockIdx.x * 64;
    int sp  = blockIdx.z;
    int tid  = threadIdx.x;
    int lane = tid & 31, w = tid >> 5;

    if (tid < 64) {
        s_sh[tid] = g_s[b*NN + i0 + tid];
        m_sh[tid] = -INFINITY;
        l_sh[tid] = 0.f;
    }

    int ig = tid >> 4;     // 0..15 -> rows ig*4..ig*4+3
    int cg = tid & 15;
    int c0 = cg * 4;
    ull acc[4][2];
    #pragma unroll
    for (int q = 0; q < 4; q++) { acc[q][0] = 0ull; acc[q][1] = 0ull; }

    const int* adjb = adj + (size_t)(b*2 + 1) * NN * NN;

    for (int jtl = 0; jtl < (NN/64)/SPLIT; jtl++) {
        int j0 = (sp * ((NN/64)/SPLIT) + jtl) * 64;
        __syncthreads();                       // prev-iter readers done
        for (int i = tid; i < 4096; i += 256)
            whs[i] = g_Wh[(b*NN + j0)*HH2 + i];
        if (tid < 64) d_sh[tid] = g_d[b*NN + j0 + tid];
        __syncthreads();

        // ---- phase P: warp w owns rows ii = w*8 .. w*8+7 -------------------
        #pragma unroll
        for (int r = 0; r < 8; r++) {
            int ii = w*8 + r;
            int i  = i0 + ii;
            float si = s_sh[ii];
            const int* arow = adjb + (size_t)i * NN + j0;
            int a1 = arow[lane];
            int a2 = arow[lane + 32];
            float v1 = si + d_sh[lane];
            float v2 = si + d_sh[lane + 32];
            float e1 = v1 > 0.f ? v1 : 0.2f * v1;
            float e2 = v2 > 0.f ? v2 : 0.2f * v2;
            e1 = a1 > 0 ? e1 : NEGV;
            e2 = a2 > 0 ? e2 : NEGV;
            float tm = fmaxf(e1, e2);
            #pragma unroll
            for (int o = 16; o > 0; o >>= 1)
                tm = fmaxf(tm, __shfl_xor_sync(0xffffffffu, tm, o));
            float mold = m_sh[ii];
            float mnew = fmaxf(mold, tm);
            float p1 = __expf(e1 - mnew);
            float p2 = __expf(e2 - mnew);
            float psum = p1 + p2;
            #pragma unroll
            for (int o = 16; o > 0; o >>= 1)
                psum += __shfl_xor_sync(0xffffffffu, psum, o);
            if (lane == 0) {
                float scale = __expf(mold - mnew);
                m_sh[ii]  = mnew;
                l_sh[ii]  = l_sh[ii] * scale + psum;
                sc_sh[ii] = scale;
            }
            Ps2[ii*64 + lane]      = pack2(p1, p1);
            Ps2[ii*64 + lane + 32] = pack2(p2, p2);
        }
        __syncthreads();

        // ---- accumulate: acc[q] = acc[q]*scale + sum_jj P[ii][jj]*Wh[jj][c]
        #pragma unroll
        for (int q = 0; q < 4; q++) {
            float sc = sc_sh[ig*4 + q];
            ull sc2 = pack2(sc, sc);
            acc[q][0] = fmul2(acc[q][0], sc2);
            acc[q][1] = fmul2(acc[q][1], sc2);
        }
        #pragma unroll 4
        for (int jj = 0; jj < 64; jj++) {
            ull wa = *(const ull*)&whs[jj*64 + c0];
            ull wb = *(const ull*)&whs[jj*64 + c0 + 2];
            #pragma unroll
            for (int q = 0; q < 4; q++) {
                ull p2 = Ps2[(ig*4 + q)*64 + jj];   // broadcast LDS.64
                acc[q][0] = ffma2(wa, p2, acc[q][0]);
                acc[q][1] = ffma2(wb, p2, acc[q][1]);
            }
        }
    }
    __syncthreads();

    // ---- emit partials -----------------------------------------------------
    if (tid < 64) {
        int r = b*NN + i0 + tid;
        g_pm[sp*ROWS_TOT + r] = m_sh[tid];
        g_pl[sp*ROWS_TOT + r] = l_sh[tid];
    }
    #pragma unroll
    for (int q = 0; q < 4; q++) {
        int ii = ig*4 + q;
        size_t r = (size_t)(sp*ROWS_TOT) + b*NN + i0 + ii;
        float v[4];
        unpack2(acc[q][0], v[0], v[1]);
        unpack2(acc[q][1], v[2], v[3]);
        *(float4*)&g_pacc[r*HH2 + c0] = make_float4(v[0], v[1], v[2], v[3]);
    }
}

// ============================================================================
// Kernel 5: combine split-K partials; final softmax normalize + elu.
// grid 4096 x 256 threads: 4 rows/block, 64 cols/row.
// ============================================================================
__global__ void k_comb(float* __restrict__ out) {
    int tid = threadIdx.x;
    int r = blockIdx.x * 4 + (tid >> 6);    // global row 0..16383
    int c = tid & 63;
    float m0 = g_pm[0*ROWS_TOT + r];
    float m1 = g_pm[1*ROWS_TOT + r];
    float m2 = g_pm[2*ROWS_TOT + r];
    float m3 = g_pm[3*ROWS_TOT + r];
    float mx = fmaxf(fmaxf(m0, m1), fmaxf(m2, m3));
    float w0 = __expf(m0 - mx), w1 = __expf(m1 - mx);
    float w2 = __expf(m2 - mx), w3 = __expf(m3 - mx);
    float l = w0*g_pl[0*ROWS_TOT + r] + w1*g_pl[1*ROWS_TOT + r]
            + w2*g_pl[2*ROWS_TOT + r] + w3*g_pl[3*ROWS_TOT + r];
    float val = w0 * g_pacc[((size_t)0*ROWS_TOT + r)*HH2 + c]
              + w1 * g_pacc[((size_t)1*ROWS_TOT + r)*HH2 + c]
              + w2 * g_pacc[((size_t)2*ROWS_TOT + r)*HH2 + c]
              + w3 * g_pacc[((size_t)3*ROWS_TOT + r)*HH2 + c];
    float z = val / l;
    out[(size_t)r*HH2 + c] = z > 0.f ? z : expm1f(z);
}

// ============================================================================
extern "C" void kernel_launch(void* const* d_in, const int* in_sizes, int n_in,
                              void* d_out, int out_size) {
    const float* hist  = (const float*)d_in[0];
    const int*   adj   = (const int*)  d_in[1];
    const float* W1    = (const float*)d_in[2];
    const float* b1    = (const float*)d_in[3];
    const float* W_ih  = (const float*)d_in[4];
    const float* W_hh  = (const float*)d_in[5];
    const float* b_ih  = (const float*)d_in[6];
    const float* b_hh  = (const float*)d_in[7];
    const float* Wg    = (const float*)d_in[8];
    const float* a_src = (const float*)d_in[9];
    const float* a_dst = (const float*)d_in[10];
    float* out = (float*)d_out;

    const size_t smem2 = (size_t)(32*256 + 64*256 + 256 + 32*9 + 64*9) * sizeof(float);
    cudaFuncSetAttribute(k_lstm, cudaFuncAttributeMaxDynamicSharedMemorySize, (int)smem2);

    k_h1  <<<2048, 256>>>(hist, W1, b1);
    k_lstm<<<256,  256, smem2>>>(W_ih, W_hh, b_ih, b_hh);
    k_wh  <<<1024, 256>>>(Wg, a_src, a_dst);
    dim3 g4(NN/64, BB, SPLIT);
    k_gat <<<g4, 256>>>(adj);
    k_comb<<<4096, 256>>>(out);
}